// round 5
// baseline (speedup 1.0000x reference)
#include <cuda_runtime.h>
#include <cstdint>

// x [B=32, T=4096, N=256] float32 -> z same shape.
#define BB 32
#define TT 4096
#define NN 256
#define BN (BB * NN)          // 8192 chains
#define NQ (BN / 4)           // 2048 quads of chains
#define CHUNK 64
#define NC (TT / CHUNK)       // 64 chunks
#define REFR 5

// Static scratch (~6.5 MB)
__device__ ulonglong2 g_mask2[NC][BN / 2];   // per-chain 64-bit sign masks (paired)
__device__ uint4      g_map4[NC][BN / 4];    // per-chain nibble-packed chunk map (u32)
__device__ uchar4     g_qin4[NC][BN / 4];    // incoming q per (chunk, chain)

// Build byte-level automaton LUTs in shared memory (blockDim.x == 256).
// For byte b and incoming state k (0..7):
//   greedy: spike at first set bit >= pos, then pos = spike + 6.
//   q_out = max(0, last_spike - 2)   (counter left after step 7)
// s_sel[b]: nibble k = q_out(k)   (PRMT-selector-ready)
// s_byt[b]: byte  k = q_out(k)
// s_spk[b]: byte  k = spike bitmask given incoming state k
__device__ __forceinline__ void build_luts(uint32_t* s_sel, uint64_t* s_byt,
                                           uint64_t* s_spk) {
    const uint32_t b = threadIdx.x;
    uint32_t sel = 0; uint64_t byt = 0, spk = 0;
    for (int k = 0; k < 8; ++k) {
        int pos = k, last = -3;
        uint32_t sp = 0;
        while (pos < 8) {
            uint32_t m = b >> pos;
            if (!m) break;
            int s = pos + __ffs((int)m) - 1;
            sp |= 1u << s;
            last = s;
            pos = s + REFR + 1;
        }
        int q = last - 2; if (q < 0) q = 0;
        sel |= (uint32_t)q << (4 * k);
        byt |= (uint64_t)q << (8 * k);
        spk |= (uint64_t)sp << (8 * k);
    }
    s_sel[b] = sel; s_byt[b] = byt; s_spk[b] = spk;
    __syncthreads();
}

// byte-packed (2 regs) -> nibble-packed u32 (q values are all <= 7)
__device__ __forceinline__ uint32_t nib_compress(uint32_t lo, uint32_t hi) {
    uint32_t t1 = lo | (lo >> 4);            // b0 = q0|q1<<4, b2 = q2|q3<<4
    uint32_t t2 = hi | (hi >> 4);
    return __byte_perm(t1, 0, 0x4420) | (__byte_perm(t2, 0, 0x4420) << 16);
}

// Pass 1: per (chain-quad, chunk): read x, build 4 sign masks + 4 chunk maps.
__global__ void __launch_bounds__(256) pass1_mask_map(const float4* __restrict__ x4) {
    __shared__ uint32_t s_sel[256];
    __shared__ uint64_t s_byt[256];
    __shared__ uint64_t s_spk[256];
    build_luts(s_sel, s_byt, s_spk);

    int tid  = blockIdx.x * 256 + threadIdx.x;   // 0 .. NQ*NC-1
    int quad = tid & (NQ - 1);
    int c    = tid >> 11;                        // / NQ
    int b    = quad >> 6;                        // / (NN/4)
    int nq   = quad & 63;

    const float4* px = x4 + ((size_t)b * TT + (size_t)c * CHUNK) * (NN / 4) + nq;

    uint64_t m0 = 0, m1 = 0, m2 = 0, m3 = 0;
    uint32_t S0l, S0h, S1l, S1h, S2l, S2h, S3l, S3h;

    // byte 7 first (right fold: S = m7), then fold m6..m0 in.
    {
        uint32_t b0 = 0, b1 = 0, b2 = 0, b3 = 0;
#pragma unroll
        for (int i = 0; i < 8; ++i) {
            float4 v = px[(size_t)(56 + i) * (NN / 4)];
            if (v.x > 0.0f) b0 |= 1u << i;
            if (v.y > 0.0f) b1 |= 1u << i;
            if (v.z > 0.0f) b2 |= 1u << i;
            if (v.w > 0.0f) b3 |= 1u << i;
        }
        m0 |= (uint64_t)b0 << 56; m1 |= (uint64_t)b1 << 56;
        m2 |= (uint64_t)b2 << 56; m3 |= (uint64_t)b3 << 56;
        uint64_t t;
        t = s_byt[b0]; S0l = (uint32_t)t; S0h = (uint32_t)(t >> 32);
        t = s_byt[b1]; S1l = (uint32_t)t; S1h = (uint32_t)(t >> 32);
        t = s_byt[b2]; S2l = (uint32_t)t; S2h = (uint32_t)(t >> 32);
        t = s_byt[b3]; S3l = (uint32_t)t; S3h = (uint32_t)(t >> 32);
    }
#pragma unroll
    for (int j = 6; j >= 0; --j) {
        uint32_t b0 = 0, b1 = 0, b2 = 0, b3 = 0;
#pragma unroll
        for (int i = 0; i < 8; ++i) {
            float4 v = px[(size_t)(j * 8 + i) * (NN / 4)];
            if (v.x > 0.0f) b0 |= 1u << i;
            if (v.y > 0.0f) b1 |= 1u << i;
            if (v.z > 0.0f) b2 |= 1u << i;
            if (v.w > 0.0f) b3 |= 1u << i;
        }
        m0 |= (uint64_t)b0 << (8 * j); m1 |= (uint64_t)b1 << (8 * j);
        m2 |= (uint64_t)b2 << (8 * j); m3 |= (uint64_t)b3 << (8 * j);
        uint32_t sel, nl, nh;
        sel = s_sel[b0]; nl = __byte_perm(S0l, S0h, sel); nh = __byte_perm(S0l, S0h, sel >> 16); S0l = nl; S0h = nh;
        sel = s_sel[b1]; nl = __byte_perm(S1l, S1h, sel); nh = __byte_perm(S1l, S1h, sel >> 16); S1l = nl; S1h = nh;
        sel = s_sel[b2]; nl = __byte_perm(S2l, S2h, sel); nh = __byte_perm(S2l, S2h, sel >> 16); S2l = nl; S2h = nh;
        sel = s_sel[b3]; nl = __byte_perm(S3l, S3h, sel); nh = __byte_perm(S3l, S3h, sel >> 16); S3l = nl; S3h = nh;
    }

    g_mask2[c][quad * 2]     = make_ulonglong2(m0, m1);
    g_mask2[c][quad * 2 + 1] = make_ulonglong2(m2, m3);
    g_map4[c][quad] = make_uint4(nib_compress(S0l, S0h), nib_compress(S1l, S1h),
                                 nib_compress(S2l, S2h), nib_compress(S3l, S3h));
}

// Pass 2: per chain — chain the 64 nibble-packed chunk maps.
__global__ void __launch_bounds__(256) pass2_compose() {
    int bn = blockIdx.x * 256 + threadIdx.x;     // 0 .. BN-1
    const uint32_t* maps = (const uint32_t*)g_map4;   // [NC][BN]
    uint8_t* qin = (uint8_t*)g_qin4;
    uint32_t q = 0;
#pragma unroll
    for (int base = 0; base < NC; base += 16) {
        uint32_t m[16];
#pragma unroll
        for (int j = 0; j < 16; ++j) m[j] = maps[(base + j) * BN + bn];
#pragma unroll
        for (int j = 0; j < 16; ++j) {
            qin[(base + j) * BN + bn] = (uint8_t)q;
            q = (m[j] >> (q * 4)) & 7u;
        }
    }
}

// Pass 3: per (chain-quad, chunk): rebuild spikes via LUT, write float4 output.
__global__ void __launch_bounds__(256) pass3_emit(float4* __restrict__ out4) {
    __shared__ uint32_t s_sel[256];
    __shared__ uint64_t s_byt[256];
    __shared__ uint64_t s_spk[256];
    build_luts(s_sel, s_byt, s_spk);

    int tid  = blockIdx.x * 256 + threadIdx.x;
    int quad = tid & (NQ - 1);
    int c    = tid >> 11;
    int b    = quad >> 6;
    int nq   = quad & 63;

    ulonglong2 ma = g_mask2[c][quad * 2];
    ulonglong2 mb = g_mask2[c][quad * 2 + 1];
    uchar4 qv = g_qin4[c][quad];

    uint64_t masks[4] = { ma.x, ma.y, mb.x, mb.y };
    uint32_t qs[4]    = { qv.x, qv.y, qv.z, qv.w };
    uint64_t spikes[4];
#pragma unroll
    for (int ch = 0; ch < 4; ++ch) {
        uint64_t mk = masks[ch];
        uint32_t q  = qs[ch];
        uint64_t sp = 0;
#pragma unroll
        for (int j = 0; j < 8; ++j) {
            uint32_t byte = (uint32_t)(mk >> (8 * j)) & 255u;
            uint64_t se = s_spk[byte];
            uint32_t sb = __byte_perm((uint32_t)se, (uint32_t)(se >> 32), q) & 255u;
            sp |= (uint64_t)sb << (8 * j);
            q = (s_sel[byte] >> (q * 4)) & 7u;
        }
        spikes[ch] = sp;
    }

    float4* po = out4 + ((size_t)b * TT + (size_t)c * CHUNK) * (NN / 4) + nq;
#pragma unroll
    for (int i = 0; i < CHUNK; ++i) {
        float4 v;
        v.x = __uint_as_float((uint32_t)((spikes[0] >> i) & 1u) * 0x3F800000u);
        v.y = __uint_as_float((uint32_t)((spikes[1] >> i) & 1u) * 0x3F800000u);
        v.z = __uint_as_float((uint32_t)((spikes[2] >> i) & 1u) * 0x3F800000u);
        v.w = __uint_as_float((uint32_t)((spikes[3] >> i) & 1u) * 0x3F800000u);
        po[(size_t)i * (NN / 4)] = v;
    }
}

extern "C" void kernel_launch(void* const* d_in, const int* in_sizes, int n_in,
                              void* d_out, int out_size) {
    (void)in_sizes; (void)n_in; (void)out_size;
    const float4* x4 = (const float4*)d_in[0];
    float4* out4 = (float4*)d_out;

    const int threads = 256;
    const int grid_big = (NQ * NC) / threads;    // 512 blocks
    const int grid_small = BN / threads;         // 32 blocks

    pass1_mask_map<<<grid_big, threads>>>(x4);
    pass2_compose<<<grid_small, threads>>>();
    pass3_emit<<<grid_big, threads>>>(out4);
}